// round 9
// baseline (speedup 1.0000x reference)
#include <cuda_runtime.h>

// ---------------------------------------------------------------------------
// DGLossVer2: fused gyro (SO3 chain, QUATERNION form) + gaussian-NLL, ONE launch.
// N=128 seqs, T=16384 steps, 3 ch. One warp handles 256 consecutive steps:
//   each lane: quat product of its 8 steps, processed as 2 half-chunks of 4
//   steps to keep register live-range small (51-reg cap, 5 blocks/SM).
//   2 shfl fold rounds -> 16-products at even lanes, 32-products at %4==0
//   residuals: log(conj(qQ)*qP) vs exp(dw16[::16]); GNLL fused (grouped logs).
// Last block performs the final reduction (threadfence pattern).
// ---------------------------------------------------------------------------

#define FULL_MASK 0xFFFFFFFFu

#define C16F  (25.0f / 391296.0f)    // W*H^2 / (128*1019*3)
#define C32F  (6.25f / 194688.0f)    // W*H^2/4 / (128*507*3)
#define CNLLF (0.5f  / 6291456.0f)   // 0.5 / (128*16384*3)

#define NBLK 1024

static __device__ float g_part[NBLK];
static __device__ unsigned int g_ticket;   // zero-init; last block resets to 0

struct Quat { float w, x, y, z; };

// Hamilton product: R(a*b) = R(a)*R(b)
__device__ __forceinline__ Quat qmul(const Quat& a, const Quat& b) {
    Quat c;
    c.w = a.w*b.w - a.x*b.x - a.y*b.y - a.z*b.z;
    c.x = a.w*b.x + a.x*b.w + a.y*b.z - a.z*b.y;
    c.y = a.w*b.y - a.x*b.z + a.y*b.w + a.z*b.x;
    c.z = a.w*b.z + a.x*b.y - a.y*b.x + a.z*b.w;
    return c;
}

// conj(a) * b  == A^T B in rotation space
__device__ __forceinline__ Quat qcmul(const Quat& a, const Quat& b) {
    Quat c;
    c.w = a.w*b.w + a.x*b.x + a.y*b.y + a.z*b.z;
    c.x = a.w*b.x - a.x*b.w - a.y*b.z + a.z*b.y;
    c.y = a.w*b.y + a.x*b.z - a.y*b.w - a.z*b.x;
    c.z = a.w*b.z - a.x*b.y + a.y*b.x - a.z*b.w;
    return c;
}

__device__ __forceinline__ Quat shfl_down_quat(const Quat& q, int d) {
    Quat r;
    r.w = __shfl_down_sync(FULL_MASK, q.w, d);
    r.x = __shfl_down_sync(FULL_MASK, q.x, d);
    r.y = __shfl_down_sync(FULL_MASK, q.y, d);
    r.z = __shfl_down_sync(FULL_MASK, q.z, d);
    return r;
}

// exp for |phi| <= ~0.04 rad: half-angle Taylor, error ~1e-12
// input already scaled: u = 0.5*DT*w_hat
__device__ __forceinline__ Quat qexp_small(float ux, float uy, float uz) {
    float a2 = ux*ux + uy*uy + uz*uz;           // |u|^2, <= ~3e-4
    float sc = 1.0f + a2 * (-(1.0f/6.0f)  + a2 * (1.0f/120.0f));  // sin|u|/|u|
    float cw = 1.0f + a2 * (-0.5f         + a2 * (1.0f/24.0f));   // cos|u|
    Quat q; q.w = cw; q.x = sc*ux; q.y = sc*uy; q.z = sc*uz;
    return q;
}

// full-range exp (dw16 samples): q = (cos(a/2), sin(a/2)/a * phi)
__device__ __forceinline__ Quat qexp_full(float x, float y, float z) {
    float a2 = x*x + y*y + z*z;
    float a  = sqrtf(a2);
    float half = 0.5f * a;
    float s = (a2 < 1e-12f) ? 0.5f : (__sinf(half) / a);
    Quat q; q.w = __cosf(half); q.x = s*x; q.y = s*y; q.z = s*z;
    return q;
}

// so3 log from quaternion, replicating reference's clipped-trace formula:
// tr(R)=4w^2-1 => c=2w^2-1 ; vee(R-R^T)=4w*qv ; r = (ang/(2 sin ang))*4w*qv
__device__ __forceinline__ void qlog_vec(const Quat& q, float r[3]) {
    float c = 2.0f * q.w * q.w - 1.0f;
    c = fminf(fmaxf(c, -1.0f + 1e-6f), 1.0f - 1e-6f);
    float f = 2.0f * acosf(c) * rsqrtf((1.0f - c) * (1.0f + c)) * q.w;
    r[0] = f * q.x; r[1] = f * q.y; r[2] = f * q.z;
}

__device__ __forceinline__ float huber3(const float r[3]) {
    float s = 0.0f;
#pragma unroll
    for (int c = 0; c < 3; c++) {
        float x = fabsf(r[c]) * 200.0f;      // 1/HUBER
        s += (x < 1.0f) ? 0.5f * x * x : x - 0.5f;
    }
    return s;
}

__global__ void __launch_bounds__(256, 5)
loss_kernel(const float* __restrict__ w_hat,
            const float* __restrict__ dw16,
            const float* __restrict__ w_gt,
            const float* __restrict__ w_mean,
            const float* __restrict__ w_std,
            float* __restrict__ out) {
    const int lane = threadIdx.x & 31;
    const int w = blockIdx.x * 8 + (threadIdx.x >> 5);   // 8192 warps total
    const int n  = w >> 6;                               // 64 warps per sequence
    const int jw = w & 63;
    const int t0 = (n << 14) + (jw << 8) + (lane << 3);  // first of 8 steps
    const int base = t0 * 3;                             // 96B-aligned float offset

    float accf = 0.0f;
    Quat M;

    // ---- two half-chunks of 4 steps: tight live ranges ----
#pragma unroll
    for (int half = 0; half < 2; half++) {
        const int off = base + half * 12;
        float h[12];
        {
            const float4* p4 = reinterpret_cast<const float4*>(w_hat + off);
            *reinterpret_cast<float4*>(&h[0]) = p4[0];
            *reinterpret_cast<float4*>(&h[4]) = p4[1];
            *reinterpret_cast<float4*>(&h[8]) = p4[2];
        }
        // gaussian NLL partial (12 components); logs grouped by 4
        {
            const float4* g4 = reinterpret_cast<const float4*>(w_gt   + off);
            const float4* m4 = reinterpret_cast<const float4*>(w_mean + off);
            const float4* s4 = reinterpret_cast<const float4*>(w_std  + off);
            float gn = 0.0f;
#pragma unroll
            for (int c = 0; c < 3; c++) {
                float4 gv = g4[c], mv = m4[c], sv = s4[c];
                float v0 = fmaxf(sv.x*sv.x, 1e-6f);
                float v1 = fmaxf(sv.y*sv.y, 1e-6f);
                float v2 = fmaxf(sv.z*sv.z, 1e-6f);
                float v3 = fmaxf(sv.w*sv.w, 1e-6f);
                float d0 = gv.x - h[4*c+0] - mv.x;
                float d1 = gv.y - h[4*c+1] - mv.y;
                float d2 = gv.z - h[4*c+2] - mv.z;
                float d3 = gv.w - h[4*c+3] - mv.w;
                gn += __fdividef(d0*d0, v0) + __fdividef(d1*d1, v1)
                    + __fdividef(d2*d2, v2) + __fdividef(d3*d3, v3);
                gn += __logf(v0 * v1 * v2 * v3);   // grouped log, min 1e-24 > FLT_MIN
            }
            accf += gn * CNLLF;
        }
        // fold 4 steps into running quat (u = 0.5*DT*h = 0.0025*h)
        Quat A = qexp_small(0.0025f*h[0], 0.0025f*h[1], 0.0025f*h[2]);
#pragma unroll
        for (int st = 1; st < 4; st++) {
            Quat R = qexp_small(0.0025f*h[3*st], 0.0025f*h[3*st+1], 0.0025f*h[3*st+2]);
            A = qmul(A, R);
        }
        M = (half == 0) ? A : qmul(M, A);
    }

    // ---- warp folds: 16-prod at even lanes, 32-prod at lanes %4==0 ----
    {
        Quat T = shfl_down_quat(M, 1); M = qmul(M, T);   // 16-product
    }
    Quat T2 = shfl_down_quat(M, 2);
    Quat Q32 = qmul(M, T2);                              // 32-product (%4==0)

    // ---- P = exp(dw16) at sample lanes (t0 % 16 == 0 <=> even lane) ----
    const bool samp = ((lane & 1) == 0);
    float dx = 0.0f, dy = 0.0f, dz = 0.0f;
    if (samp) { dx = dw16[base]; dy = dw16[base+1]; dz = dw16[base+2]; }
    Quat P = qexp_full(dx, dy, dz);                      // identity on odd lanes
    Quat Pn = shfl_down_quat(P, 2);

    // ---- 16-level residual (16 per warp) ----
    if (samp) {
        int il = (jw << 4) + (lane >> 1);
        if (il >= 5) {
            Quat Mr = qcmul(M, P);                       // Q16^T P
            float r[3]; qlog_vec(Mr, r);
            accf += huber3(r) * C16F;
        }
    }
    // ---- 32-level residual (8 per warp) ----
    if ((lane & 3) == 0) {
        int i32 = (jw << 3) + (lane >> 2);
        if (i32 >= 5) {
            Quat P2 = qmul(P, Pn);
            Quat Mr = qcmul(Q32, P2);
            float r[3]; qlog_vec(Mr, r);
            accf += huber3(r) * C32F;
        }
    }

    // ---- block reduce ----
#pragma unroll
    for (int d = 16; d > 0; d >>= 1)
        accf += __shfl_down_sync(FULL_MASK, accf, d);

    __shared__ float ssum[8];
    __shared__ bool s_last;
    if (lane == 0) ssum[threadIdx.x >> 5] = accf;
    __syncthreads();
    if (threadIdx.x == 0) {
        float t = 0.0f;
#pragma unroll
        for (int i = 0; i < 8; i++) t += ssum[i];
        g_part[blockIdx.x] = t;
        __threadfence();
        unsigned int tk = atomicAdd(&g_ticket, 1u);
        s_last = (tk == NBLK - 1u);
    }
    __syncthreads();

    // ---- last block: final reduction + output + ticket reset ----
    if (s_last) {
        double v = 0.0;
#pragma unroll
        for (int i = 0; i < NBLK / 256; i++)
            v += (double)g_part[threadIdx.x + 256 * i];
#pragma unroll
        for (int d = 16; d > 0; d >>= 1)
            v += __shfl_down_sync(FULL_MASK, v, d);
        __shared__ double sd[8];
        if (lane == 0) sd[threadIdx.x >> 5] = v;
        __syncthreads();
        if (threadIdx.x == 0) {
            double t = 0.0;
#pragma unroll
            for (int i = 0; i < 8; i++) t += sd[i];
            out[0] = (float)t;
            g_ticket = 0;          // reset for next graph replay
        }
    }
}

extern "C" void kernel_launch(void* const* d_in, const int* in_sizes, int n_in,
                              void* d_out, int out_size) {
    const float* w_hat  = (const float*)d_in[0];
    const float* dw16   = (const float*)d_in[1];
    const float* w_gt   = (const float*)d_in[2];
    const float* w_mean = (const float*)d_in[3];
    const float* w_std  = (const float*)d_in[4];
    float* out = (float*)d_out;

    // 8192 warps -> 1024 blocks x 256 threads, single launch
    loss_kernel<<<NBLK, 256>>>(w_hat, dw16, w_gt, w_mean, w_std, out);
}

// round 10
// speedup vs baseline: 1.1204x; 1.1204x over previous
#include <cuda_runtime.h>

// ---------------------------------------------------------------------------
// DGLossVer2: fused gyro (SO3 chain, QUATERNION form) + gaussian-NLL, ONE launch.
// N=128 seqs, T=16384 steps, 3 ch. One warp handles 256 consecutive steps.
// ALL streamed loads are coalesced (float4, thread t <- base + 32i + t):
//   - GNLL is a pure reduction: consumed directly in coalesced order.
//   - w_hat is staged through a per-warp smem buffer to restore step order
//     for the quat chain (8 steps/thread, 7 in-thread qmuls).
// 2 shfl fold rounds -> 16-products at even lanes, 32-products at %4==0.
// Residuals: log(conj(qQ)*qP) vs exp(dw16[::16]).
// Last block performs the final reduction (threadfence pattern).
// ---------------------------------------------------------------------------

#define FULL_MASK 0xFFFFFFFFu

#define C16F  (25.0f / 391296.0f)    // W*H^2 / (128*1019*3)
#define C32F  (6.25f / 194688.0f)    // W*H^2/4 / (128*507*3)
#define CNLLF (0.5f  / 6291456.0f)   // 0.5 / (128*16384*3)

#define NBLK 1024

static __device__ float g_part[NBLK];
static __device__ unsigned int g_ticket;   // zero-init; last block resets to 0

struct Quat { float w, x, y, z; };

// Hamilton product: R(a*b) = R(a)*R(b)
__device__ __forceinline__ Quat qmul(const Quat& a, const Quat& b) {
    Quat c;
    c.w = a.w*b.w - a.x*b.x - a.y*b.y - a.z*b.z;
    c.x = a.w*b.x + a.x*b.w + a.y*b.z - a.z*b.y;
    c.y = a.w*b.y - a.x*b.z + a.y*b.w + a.z*b.x;
    c.z = a.w*b.z + a.x*b.y - a.y*b.x + a.z*b.w;
    return c;
}

// conj(a) * b  == A^T B in rotation space
__device__ __forceinline__ Quat qcmul(const Quat& a, const Quat& b) {
    Quat c;
    c.w = a.w*b.w + a.x*b.x + a.y*b.y + a.z*b.z;
    c.x = a.w*b.x - a.x*b.w - a.y*b.z + a.z*b.y;
    c.y = a.w*b.y + a.x*b.z - a.y*b.w - a.z*b.x;
    c.z = a.w*b.z - a.x*b.y + a.y*b.x - a.z*b.w;
    return c;
}

__device__ __forceinline__ Quat shfl_down_quat(const Quat& q, int d) {
    Quat r;
    r.w = __shfl_down_sync(FULL_MASK, q.w, d);
    r.x = __shfl_down_sync(FULL_MASK, q.x, d);
    r.y = __shfl_down_sync(FULL_MASK, q.y, d);
    r.z = __shfl_down_sync(FULL_MASK, q.z, d);
    return r;
}

// exp for |phi| <= ~0.04 rad: half-angle Taylor, error ~1e-12
// input already scaled: u = 0.5*DT*w_hat
__device__ __forceinline__ Quat qexp_small(float ux, float uy, float uz) {
    float a2 = ux*ux + uy*uy + uz*uz;           // |u|^2, <= ~3e-4
    float sc = 1.0f + a2 * (-(1.0f/6.0f)  + a2 * (1.0f/120.0f));  // sin|u|/|u|
    float cw = 1.0f + a2 * (-0.5f         + a2 * (1.0f/24.0f));   // cos|u|
    Quat q; q.w = cw; q.x = sc*ux; q.y = sc*uy; q.z = sc*uz;
    return q;
}

// full-range exp (dw16 samples): q = (cos(a/2), sin(a/2)/a * phi)
__device__ __forceinline__ Quat qexp_full(float x, float y, float z) {
    float a2 = x*x + y*y + z*z;
    float a  = sqrtf(a2);
    float half = 0.5f * a;
    float s = (a2 < 1e-12f) ? 0.5f : (__sinf(half) / a);
    Quat q; q.w = __cosf(half); q.x = s*x; q.y = s*y; q.z = s*z;
    return q;
}

// so3 log from quaternion, replicating reference's clipped-trace formula:
// tr(R)=4w^2-1 => c=2w^2-1 ; vee(R-R^T)=4w*qv ; r = (ang/(2 sin ang))*4w*qv
__device__ __forceinline__ void qlog_vec(const Quat& q, float r[3]) {
    float c = 2.0f * q.w * q.w - 1.0f;
    c = fminf(fmaxf(c, -1.0f + 1e-6f), 1.0f - 1e-6f);
    float f = 2.0f * acosf(c) * rsqrtf((1.0f - c) * (1.0f + c)) * q.w;
    r[0] = f * q.x; r[1] = f * q.y; r[2] = f * q.z;
}

__device__ __forceinline__ float huber3(const float r[3]) {
    float s = 0.0f;
#pragma unroll
    for (int c = 0; c < 3; c++) {
        float x = fabsf(r[c]) * 200.0f;      // 1/HUBER
        s += (x < 1.0f) ? 0.5f * x * x : x - 0.5f;
    }
    return s;
}

__global__ void __launch_bounds__(256, 4)
loss_kernel(const float* __restrict__ w_hat,
            const float* __restrict__ dw16,
            const float* __restrict__ w_gt,
            const float* __restrict__ w_mean,
            const float* __restrict__ w_std,
            float* __restrict__ out) {
    const int lane = threadIdx.x & 31;
    const int wid  = threadIdx.x >> 5;
    const int w = blockIdx.x * 8 + wid;                  // 8192 warps total
    const int jw = w & 63;                               // warp within sequence
    // warp owns 256 steps = 768 floats = 192 float4, base in float4 units:
    const int wb4 = w * 192;
    const int base = w * 768 + lane * 24;                // this thread's 8 steps (floats)

    __shared__ float4 sm4[8 * 192];                      // 24KB: w_hat staging

    // ---- coalesced loads: thread t <- float4 (wb4 + 32*i + t) ----
    const float4* h4p = reinterpret_cast<const float4*>(w_hat)  + wb4 + lane;
    const float4* g4p = reinterpret_cast<const float4*>(w_gt)   + wb4 + lane;
    const float4* m4p = reinterpret_cast<const float4*>(w_mean) + wb4 + lane;
    const float4* s4p = reinterpret_cast<const float4*>(w_std)  + wb4 + lane;

    float4 h4[6];
#pragma unroll
    for (int i = 0; i < 6; i++) h4[i] = h4p[32 * i];
    // stage w_hat into smem (coalesced STS.128)
#pragma unroll
    for (int i = 0; i < 6; i++) sm4[wid * 192 + 32 * i + lane] = h4[i];

    // ---- gaussian NLL on coalesced data (reduction: order-free) ----
    float accf = 0.0f;
    {
        float gn = 0.0f;
#pragma unroll
        for (int i = 0; i < 6; i++) {
            float4 gv = g4p[32 * i];
            float4 mv = m4p[32 * i];
            float4 sv = s4p[32 * i];
            float v0 = fmaxf(sv.x*sv.x, 1e-6f);
            float v1 = fmaxf(sv.y*sv.y, 1e-6f);
            float v2 = fmaxf(sv.z*sv.z, 1e-6f);
            float v3 = fmaxf(sv.w*sv.w, 1e-6f);
            float d0 = gv.x - h4[i].x - mv.x;
            float d1 = gv.y - h4[i].y - mv.y;
            float d2 = gv.z - h4[i].z - mv.z;
            float d3 = gv.w - h4[i].w - mv.w;
            gn += __fdividef(d0*d0, v0) + __fdividef(d1*d1, v1)
                + __fdividef(d2*d2, v2) + __fdividef(d3*d3, v3);
            gn += __logf(v0 * v1 * v2 * v3);   // grouped log, min 1e-24 > FLT_MIN
        }
        accf = gn * CNLLF;
    }

    // ---- dw16 sample for even lanes (issue early) ----
    const bool samp = ((lane & 1) == 0);
    float dx = 0.0f, dy = 0.0f, dz = 0.0f;
    if (samp) { dx = dw16[base]; dy = dw16[base+1]; dz = dw16[base+2]; }

    __syncwarp();

    // ---- read own 8 steps from smem, fold into quat chain ----
    float h[24];
    {
        const float4* msrc = &sm4[wid * 192 + lane * 6];
#pragma unroll
        for (int j = 0; j < 6; j++)
            *reinterpret_cast<float4*>(&h[4*j]) = msrc[j];
    }
    // u = 0.5*DT*h = 0.0025*h
    Quat M = qexp_small(0.0025f*h[0], 0.0025f*h[1], 0.0025f*h[2]);
#pragma unroll
    for (int st = 1; st < 8; st++) {
        Quat R = qexp_small(0.0025f*h[3*st], 0.0025f*h[3*st+1], 0.0025f*h[3*st+2]);
        M = qmul(M, R);
    }

    // ---- warp folds: 16-prod at even lanes, 32-prod at lanes %4==0 ----
    {
        Quat T = shfl_down_quat(M, 1); M = qmul(M, T);   // 16-product
    }
    Quat T2 = shfl_down_quat(M, 2);
    Quat Q32 = qmul(M, T2);                              // 32-product (%4==0)

    Quat P = qexp_full(dx, dy, dz);                      // identity on odd lanes
    Quat Pn = shfl_down_quat(P, 2);

    // ---- 16-level residual (16 per warp) ----
    if (samp) {
        int il = (jw << 4) + (lane >> 1);
        if (il >= 5) {
            Quat Mr = qcmul(M, P);                       // Q16^T P
            float r[3]; qlog_vec(Mr, r);
            accf += huber3(r) * C16F;
        }
    }
    // ---- 32-level residual (8 per warp) ----
    if ((lane & 3) == 0) {
        int i32 = (jw << 3) + (lane >> 2);
        if (i32 >= 5) {
            Quat P2 = qmul(P, Pn);
            Quat Mr = qcmul(Q32, P2);
            float r[3]; qlog_vec(Mr, r);
            accf += huber3(r) * C32F;
        }
    }

    // ---- block reduce ----
#pragma unroll
    for (int d = 16; d > 0; d >>= 1)
        accf += __shfl_down_sync(FULL_MASK, accf, d);

    __shared__ float ssum[8];
    __shared__ bool s_last;
    if (lane == 0) ssum[wid] = accf;
    __syncthreads();
    if (threadIdx.x == 0) {
        float t = 0.0f;
#pragma unroll
        for (int i = 0; i < 8; i++) t += ssum[i];
        g_part[blockIdx.x] = t;
        __threadfence();
        unsigned int tk = atomicAdd(&g_ticket, 1u);
        s_last = (tk == NBLK - 1u);
    }
    __syncthreads();

    // ---- last block: final reduction + output + ticket reset ----
    if (s_last) {
        double v = 0.0;
#pragma unroll
        for (int i = 0; i < NBLK / 256; i++)
            v += (double)g_part[threadIdx.x + 256 * i];
#pragma unroll
        for (int d = 16; d > 0; d >>= 1)
            v += __shfl_down_sync(FULL_MASK, v, d);
        __shared__ double sd[8];
        if (lane == 0) sd[wid] = v;
        __syncthreads();
        if (threadIdx.x == 0) {
            double t = 0.0;
#pragma unroll
            for (int i = 0; i < 8; i++) t += sd[i];
            out[0] = (float)t;
            g_ticket = 0;          // reset for next graph replay
        }
    }
}

extern "C" void kernel_launch(void* const* d_in, const int* in_sizes, int n_in,
                              void* d_out, int out_size) {
    const float* w_hat  = (const float*)d_in[0];
    const float* dw16   = (const float*)d_in[1];
    const float* w_gt   = (const float*)d_in[2];
    const float* w_mean = (const float*)d_in[3];
    const float* w_std  = (const float*)d_in[4];
    float* out = (float*)d_out;

    // 8192 warps -> 1024 blocks x 256 threads, single launch
    loss_kernel<<<NBLK, 256>>>(w_hat, dw16, w_gt, w_mean, w_std, out);
}

// round 13
// speedup vs baseline: 1.1747x; 1.0485x over previous
#include <cuda_runtime.h>
#include <cstdint>

// ---------------------------------------------------------------------------
// DGLossVer2: fused gyro (SO3 chain, QUATERNION form) + gaussian-NLL, ONE launch.
// N=128 seqs, T=16384 steps, 3 ch. One warp handles 256 consecutive steps.
// ALL streamed loads coalesced (float4, thread t <- base + 32i + t):
//   - w_hat: cp.async GMEM->SMEM (no register round-trip), read back via LDS
//     both for the NLL gap term and, in step order, for the quat chain.
//   - g/m/s: streamed LDG.128, deep software pipeline (registers freed by
//     cp.async make room).
// 2 shfl fold rounds -> 16-products at even lanes, 32-products at %4==0.
// Residuals: log(conj(qQ)*qP) vs exp(dw16[::16]).
// Last block performs the final reduction (threadfence pattern).
// ---------------------------------------------------------------------------

#define FULL_MASK 0xFFFFFFFFu

#define C16F  (25.0f / 391296.0f)    // W*H^2 / (128*1019*3)
#define C32F  (6.25f / 194688.0f)    // W*H^2/4 / (128*507*3)
#define CNLLF (0.5f  / 6291456.0f)   // 0.5 / (128*16384*3)

#define NBLK 1024

static __device__ float g_part[NBLK];
static __device__ unsigned int g_ticket;   // zero-init; last block resets to 0

struct Quat { float w, x, y, z; };

__device__ __forceinline__ Quat qmul(const Quat& a, const Quat& b) {
    Quat c;
    c.w = a.w*b.w - a.x*b.x - a.y*b.y - a.z*b.z;
    c.x = a.w*b.x + a.x*b.w + a.y*b.z - a.z*b.y;
    c.y = a.w*b.y - a.x*b.z + a.y*b.w + a.z*b.x;
    c.z = a.w*b.z + a.x*b.y - a.y*b.x + a.z*b.w;
    return c;
}

// conj(a) * b  == A^T B in rotation space
__device__ __forceinline__ Quat qcmul(const Quat& a, const Quat& b) {
    Quat c;
    c.w = a.w*b.w + a.x*b.x + a.y*b.y + a.z*b.z;
    c.x = a.w*b.x - a.x*b.w - a.y*b.z + a.z*b.y;
    c.y = a.w*b.y + a.x*b.z - a.y*b.w - a.z*b.x;
    c.z = a.w*b.z - a.x*b.y + a.y*b.x - a.z*b.w;
    return c;
}

__device__ __forceinline__ Quat shfl_down_quat(const Quat& q, int d) {
    Quat r;
    r.w = __shfl_down_sync(FULL_MASK, q.w, d);
    r.x = __shfl_down_sync(FULL_MASK, q.x, d);
    r.y = __shfl_down_sync(FULL_MASK, q.y, d);
    r.z = __shfl_down_sync(FULL_MASK, q.z, d);
    return r;
}

// exp for |phi| <= ~0.04 rad: half-angle Taylor, error ~1e-12
// input already scaled: u = 0.5*DT*w_hat
__device__ __forceinline__ Quat qexp_small(float ux, float uy, float uz) {
    float a2 = ux*ux + uy*uy + uz*uz;
    float sc = 1.0f + a2 * (-(1.0f/6.0f)  + a2 * (1.0f/120.0f));  // sin|u|/|u|
    float cw = 1.0f + a2 * (-0.5f         + a2 * (1.0f/24.0f));   // cos|u|
    Quat q; q.w = cw; q.x = sc*ux; q.y = sc*uy; q.z = sc*uz;
    return q;
}

// full-range exp (dw16 samples): q = (cos(a/2), sin(a/2)/a * phi)
__device__ __forceinline__ Quat qexp_full(float x, float y, float z) {
    float a2 = x*x + y*y + z*z;
    float a  = sqrtf(a2);
    float half = 0.5f * a;
    float s = (a2 < 1e-12f) ? 0.5f : (__sinf(half) / a);
    Quat q; q.w = __cosf(half); q.x = s*x; q.y = s*y; q.z = s*z;
    return q;
}

// so3 log from quaternion, replicating reference's clipped-trace formula:
// tr(R)=4w^2-1 => c=2w^2-1 ; vee(R-R^T)=4w*qv ; r = (ang/(2 sin ang))*4w*qv
__device__ __forceinline__ void qlog_vec(const Quat& q, float r[3]) {
    float c = 2.0f * q.w * q.w - 1.0f;
    c = fminf(fmaxf(c, -1.0f + 1e-6f), 1.0f - 1e-6f);
    float f = 2.0f * acosf(c) * rsqrtf((1.0f - c) * (1.0f + c)) * q.w;
    r[0] = f * q.x; r[1] = f * q.y; r[2] = f * q.z;
}

__device__ __forceinline__ float huber3(const float r[3]) {
    float s = 0.0f;
#pragma unroll
    for (int c = 0; c < 3; c++) {
        float x = fabsf(r[c]) * 200.0f;      // 1/HUBER
        s += (x < 1.0f) ? 0.5f * x * x : x - 0.5f;
    }
    return s;
}

__device__ __forceinline__ void cp_async16(unsigned int saddr, const void* gptr) {
    asm volatile("cp.async.cg.shared.global [%0], [%1], 16;\n"
                 :: "r"(saddr), "l"(gptr) : "memory");
}

__global__ void __launch_bounds__(256, 4)
loss_kernel(const float* __restrict__ w_hat,
            const float* __restrict__ dw16,
            const float* __restrict__ w_gt,
            const float* __restrict__ w_mean,
            const float* __restrict__ w_std,
            float* __restrict__ out) {
    const int lane = threadIdx.x & 31;
    const int wid  = threadIdx.x >> 5;
    const int w = blockIdx.x * 8 + wid;                  // 8192 warps total
    const int jw = w & 63;                               // warp within sequence
    // warp owns 256 steps = 768 floats = 192 float4
    const int wb4 = w * 192;
    const int base = w * 768 + lane * 24;                // this thread's 8 steps (floats)

    __shared__ float4 sm4[8 * 192];                      // 24KB: w_hat staging

    // ---- w_hat: cp.async straight into smem (no register round-trip) ----
    {
        unsigned int sdst =
            (unsigned int)__cvta_generic_to_shared(&sm4[wid * 192 + lane]);
        const float4* hsrc = reinterpret_cast<const float4*>(w_hat) + wb4 + lane;
#pragma unroll
        for (int i = 0; i < 6; i++)
            cp_async16(sdst + i * 32 * 16, hsrc + 32 * i);
        asm volatile("cp.async.commit_group;\n" ::: "memory");
    }

    // ---- dw16 sample for even lanes (issue early, long latency covered) ----
    const bool samp = ((lane & 1) == 0);
    float dx = 0.0f, dy = 0.0f, dz = 0.0f;
    if (samp) { dx = dw16[base]; dy = dw16[base+1]; dz = dw16[base+2]; }

    // ---- wait for h staging (needed by NLL gap term), warp-local visibility ----
    asm volatile("cp.async.wait_group 0;\n" ::: "memory");
    __syncwarp();

    // ---- gaussian NLL on coalesced data (reduction: order-free) ----
    const float4* g4p = reinterpret_cast<const float4*>(w_gt)   + wb4 + lane;
    const float4* m4p = reinterpret_cast<const float4*>(w_mean) + wb4 + lane;
    const float4* s4p = reinterpret_cast<const float4*>(w_std)  + wb4 + lane;
    const float4* hsm = &sm4[wid * 192 + lane];

    float accf = 0.0f;
    {
        float gn = 0.0f;
#pragma unroll
        for (int i = 0; i < 6; i++) {
            float4 gv = g4p[32 * i];
            float4 mv = m4p[32 * i];
            float4 sv = s4p[32 * i];
            float4 hv = hsm[32 * i];                     // LDS.128, conflict-free
            float v0 = fmaxf(sv.x*sv.x, 1e-6f);
            float v1 = fmaxf(sv.y*sv.y, 1e-6f);
            float v2 = fmaxf(sv.z*sv.z, 1e-6f);
            float v3 = fmaxf(sv.w*sv.w, 1e-6f);
            float d0 = gv.x - hv.x - mv.x;
            float d1 = gv.y - hv.y - mv.y;
            float d2 = gv.z - hv.z - mv.z;
            float d3 = gv.w - hv.w - mv.w;
            gn += __fdividef(d0*d0, v0) + __fdividef(d1*d1, v1)
                + __fdividef(d2*d2, v2) + __fdividef(d3*d3, v3);
            gn += __logf(v0 * v1 * v2 * v3);   // grouped log, min 1e-24 > FLT_MIN
        }
        accf = gn * CNLLF;
    }

    // ---- read own 8 steps (step order) from smem, fold into quat chain ----
    float h[24];
    {
        const float4* msrc = &sm4[wid * 192 + lane * 6];
#pragma unroll
        for (int j = 0; j < 6; j++)
            *reinterpret_cast<float4*>(&h[4*j]) = msrc[j];
    }
    // u = 0.5*DT*h = 0.0025*h
    Quat M = qexp_small(0.0025f*h[0], 0.0025f*h[1], 0.0025f*h[2]);
#pragma unroll
    for (int st = 1; st < 8; st++) {
        Quat R = qexp_small(0.0025f*h[3*st], 0.0025f*h[3*st+1], 0.0025f*h[3*st+2]);
        M = qmul(M, R);
    }

    // ---- warp folds: 16-prod at even lanes, 32-prod at lanes %4==0 ----
    {
        Quat T = shfl_down_quat(M, 1); M = qmul(M, T);   // 16-product
    }
    Quat T2 = shfl_down_quat(M, 2);
    Quat Q32 = qmul(M, T2);                              // 32-product (%4==0)

    Quat P = qexp_full(dx, dy, dz);                      // identity on odd lanes
    Quat Pn = shfl_down_quat(P, 2);

    // ---- 16-level residual (16 per warp) ----
    if (samp) {
        int il = (jw << 4) + (lane >> 1);
        if (il >= 5) {
            Quat Mr = qcmul(M, P);                       // Q16^T P
            float r[3]; qlog_vec(Mr, r);
            accf += huber3(r) * C16F;
        }
    }
    // ---- 32-level residual (8 per warp) ----
    if ((lane & 3) == 0) {
        int i32 = (jw << 3) + (lane >> 2);
        if (i32 >= 5) {
            Quat P2 = qmul(P, Pn);
            Quat Mr = qcmul(Q32, P2);
            float r[3]; qlog_vec(Mr, r);
            accf += huber3(r) * C32F;
        }
    }

    // ---- block reduce ----
#pragma unroll
    for (int d = 16; d > 0; d >>= 1)
        accf += __shfl_down_sync(FULL_MASK, accf, d);

    __shared__ float ssum[8];
    __shared__ bool s_last;
    if (lane == 0) ssum[wid] = accf;
    __syncthreads();
    if (threadIdx.x == 0) {
        float t = 0.0f;
#pragma unroll
        for (int i = 0; i < 8; i++) t += ssum[i];
        g_part[blockIdx.x] = t;
        __threadfence();
        unsigned int tk = atomicAdd(&g_ticket, 1u);
        s_last = (tk == NBLK - 1u);
    }
    __syncthreads();

    // ---- last block: final reduction + output + ticket reset ----
    if (s_last) {
        double v = 0.0;
#pragma unroll
        for (int i = 0; i < NBLK / 256; i++)
            v += (double)g_part[threadIdx.x + 256 * i];
#pragma unroll
        for (int d = 16; d > 0; d >>= 1)
            v += __shfl_down_sync(FULL_MASK, v, d);
        __shared__ double sd[8];
        if (lane == 0) sd[wid] = v;
        __syncthreads();
        if (threadIdx.x == 0) {
            double t = 0.0;
#pragma unroll
            for (int i = 0; i < 8; i++) t += sd[i];
            out[0] = (float)t;
            g_ticket = 0;          // reset for next graph replay
        }
    }
}

extern "C" void kernel_launch(void* const* d_in, const int* in_sizes, int n_in,
                              void* d_out, int out_size) {
    const float* w_hat  = (const float*)d_in[0];
    const float* dw16   = (const float*)d_in[1];
    const float* w_gt   = (const float*)d_in[2];
    const float* w_mean = (const float*)d_in[3];
    const float* w_std  = (const float*)d_in[4];
    float* out = (float*)d_out;

    // 8192 warps -> 1024 blocks x 256 threads, single launch
    loss_kernel<<<NBLK, 256>>>(w_hat, dw16, w_gt, w_mean, w_std, out);
}